// round 17
// baseline (speedup 1.0000x reference)
#include <cuda_runtime.h>
#include <cuda_bf16.h>
#include <cuda_fp16.h>
#include <cstdint>

#define N_NODES 50000
#define N_PAD   50048              // 391 * 128
#define N_EDGES 25000
#define NNZ     800000
#define DIM     256

#define CH_E ((N_EDGES + 1023) / 1024)   // 25
#define CH_N ((N_NODES + 1023) / 1024)   // 49

// ---------------- scratch ----------------------------------------------------
__device__ __align__(16) __half g_Zh [N_NODES * DIM];     // fp16(X@W + b)  25.6MB
__device__ __align__(16) __half g_S2h[N_EDGES * DIM];     // fp16 step2     12.8MB
__device__ __align__(16) float  g_Wt [DIM * DIM];         // tf32-rounded W^T [n][k]
__device__ int   g_deg_v[N_NODES];
__device__ int   g_deg_e[N_EDGES];
__device__ float g_dv[N_NODES];
__device__ float g_de[N_EDGES];
__device__ int   g_off_e[N_EDGES + 1];
__device__ int   g_off_n[N_NODES + 1];
__device__ int   g_rank_v[NNZ];
__device__ int   g_rank_e[NNZ];
__device__ int   g_adj_e[NNZ];
__device__ int   g_adj_n[NNZ];
__device__ int   g_part_e[32];
__device__ int   g_part_n[64];
__device__ int   g_is64;

// ---------------- helpers ----------------------------------------------------
__device__ __forceinline__ int idx_at(const void* p, int i, int is64) {
    if (is64) return (int)(((const long long*)p)[i]);
    return ((const int*)p)[i];
}
__device__ __forceinline__ uint32_t f2tf32(float f) {
    uint32_t r;
    asm("cvt.rna.tf32.f32 %0, %1;" : "=r"(r) : "f"(f));
    return r;
}
__device__ __forceinline__ void mma_tf32(float* c, uint32_t a0, uint32_t a1,
                                         uint32_t a2, uint32_t a3,
                                         uint32_t b0, uint32_t b1) {
    asm volatile(
        "mma.sync.aligned.m16n8k8.row.col.f32.tf32.tf32.f32 "
        "{%0,%1,%2,%3}, {%4,%5,%6,%7}, {%8,%9}, {%0,%1,%2,%3};\n"
        : "+f"(c[0]), "+f"(c[1]), "+f"(c[2]), "+f"(c[3])
        : "r"(a0), "r"(a1), "r"(a2), "r"(a3), "r"(b0), "r"(b1));
}
__device__ __forceinline__ void cp_async16(void* smem_dst, const void* gsrc) {
    uint32_t s;
    asm("{ .reg .u64 t; cvta.to.shared.u64 t, %1; cvt.u32.u64 %0, t; }"
        : "=r"(s) : "l"(smem_dst));
    asm volatile("cp.async.cg.shared.global [%0], [%1], 16;" :: "r"(s), "l"(gsrc));
}
// accumulate 4 fp16 lanes (one uint2) into float acc[4], scaled by s
__device__ __forceinline__ void acc4(float* a, uint2 v, float s) {
    __half2 h0 = *(__half2*)&v.x, h1 = *(__half2*)&v.y;
    float2 f0 = __half22float2(h0), f1 = __half22float2(h1);
    a[0] = fmaf(f0.x, s, a[0]); a[1] = fmaf(f0.y, s, a[1]);
    a[2] = fmaf(f1.x, s, a[2]); a[3] = fmaf(f1.y, s, a[3]);
}

// ---------------- detect index dtype (32 threads, 64 qwords) -----------------
__global__ void detect_kernel(const void* node_idx) {
    const unsigned long long* q = (const unsigned long long*)node_idx;
    int t = threadIdx.x;
    int bad = ((q[t] >> 32) != 0ull) || ((q[t + 32] >> 32) != 0ull);
    bad = __any_sync(0xffffffffu, bad);
    if (t == 0) g_is64 = bad ? 0 : 1;
}

// ---------------- zero degree counters (off critical path, side stream) ------
__global__ void zero_kernel() {
    int i = blockIdx.x * blockDim.x + threadIdx.x;
    if (i < N_NODES) g_deg_v[i] = 0;
    if (i < N_EDGES) g_deg_e[i] = 0;
}

// ---------------- degree histogram + rank capture, split per side ------------
__global__ void count_e_kernel(const void* ei) {
    int i = blockIdx.x * blockDim.x + threadIdx.x;
    if (i >= NNZ) return;
    int e = idx_at(ei, i, g_is64);
    g_rank_e[i] = atomicAdd(&g_deg_e[e], 1);
}
__global__ void count_v_kernel(const void* ni) {
    int i = blockIdx.x * blockDim.x + threadIdx.x;
    if (i >= NNZ) return;
    int n = idx_at(ni, i, g_is64);
    g_rank_v[i] = atomicAdd(&g_deg_v[n], 1);
}

// ---------------- convert W -> transposed tf32-rounded fp32 ------------------
__global__ void convert_w_kernel(const float* __restrict__ W) {
    int n = blockIdx.x;
    int k = threadIdx.x;
    float w = W[(size_t)k * DIM + n];
    g_Wt[n * DIM + k] = __uint_as_float(f2tf32(w));
}

// ---------------- GEMM half: tf32 TC, A reg-prefetch, B cp.async db ----------
// Computes Zh[:, n0:n0+128].  128x128 tile, K-chunks of 32, 8 warps.
#define SAF 36
__global__ __launch_bounds__(256, 2)
void gemm_tf32_kernel(const float* __restrict__ X,
                      const float* __restrict__ bias, int n0) {
    __shared__ __align__(16) float As[128][SAF];
    __shared__ __align__(16) float Bs[2][128][SAF];

    int t    = threadIdx.x;
    int warp = t >> 5, lane = t & 31;
    int wm = warp >> 2, wn = warp & 3;
    int g  = lane >> 2, q = lane & 3;
    int m0 = blockIdx.x * 128;

    float acc[4][4][4];
    #pragma unroll
    for (int i = 0; i < 4; i++)
        #pragma unroll
        for (int j = 0; j < 4; j++)
            #pragma unroll
            for (int r = 0; r < 4; r++) acc[i][j][r] = 0.0f;

    int lrow = t >> 1;        // 0..127
    int lseg = t & 1;         // 16-float segment
    int gr = m0 + lrow;

    // issue cp.async for B chunk 0 into Bs[0]
    {
        const float* bsrc = &g_Wt[(n0 + lrow) * DIM + 0 + lseg * 16];
        #pragma unroll
        for (int p = 0; p < 4; p++)
            cp_async16(&Bs[0][lrow][lseg * 16 + p * 4], bsrc + p * 4);
        asm volatile("cp.async.commit_group;" ::: "memory");
    }

    // prefetch A chunk 0 into registers
    float vf[16];
    {
        if (gr < N_NODES) {
            const float4* src = (const float4*)&X[(size_t)gr * DIM + 0 + lseg * 16];
            float4 f0 = src[0], f1 = src[1], f2 = src[2], f3 = src[3];
            vf[0]=f0.x; vf[1]=f0.y; vf[2]=f0.z; vf[3]=f0.w;
            vf[4]=f1.x; vf[5]=f1.y; vf[6]=f1.z; vf[7]=f1.w;
            vf[8]=f2.x; vf[9]=f2.y; vf[10]=f2.z; vf[11]=f2.w;
            vf[12]=f3.x; vf[13]=f3.y; vf[14]=f3.z; vf[15]=f3.w;
        } else {
            #pragma unroll
            for (int k = 0; k < 16; k++) vf[k] = 0.0f;
        }
    }

    #pragma unroll
    for (int kc = 0; kc < 8; kc++) {
        int k0 = kc * 32;
        int buf = kc & 1;
        // A: tf32-round prefetched regs -> smem
        {
            uint32_t tv[16];
            #pragma unroll
            for (int k = 0; k < 16; k++) tv[k] = f2tf32(vf[k]);
            #pragma unroll
            for (int p = 0; p < 4; p++)
                *(uint4*)&As[lrow][lseg * 16 + p * 4] = ((uint4*)tv)[p];
        }
        // issue cp.async for NEXT B chunk into the other buffer
        if (kc < 7) {
            const float* bsrc = &g_Wt[(n0 + lrow) * DIM + k0 + 32 + lseg * 16];
            #pragma unroll
            for (int p = 0; p < 4; p++)
                cp_async16(&Bs[buf ^ 1][lrow][lseg * 16 + p * 4], bsrc + p * 4);
            asm volatile("cp.async.commit_group;" ::: "memory");
            asm volatile("cp.async.wait_group 1;" ::: "memory");
        } else {
            asm volatile("cp.async.wait_group 0;" ::: "memory");
        }
        __syncthreads();

        // prefetch NEXT A chunk while MMAs run on this one
        if (kc < 7) {
            if (gr < N_NODES) {
                const float4* src = (const float4*)&X[(size_t)gr * DIM + k0 + 32 + lseg * 16];
                float4 f0 = src[0], f1 = src[1], f2 = src[2], f3 = src[3];
                vf[0]=f0.x; vf[1]=f0.y; vf[2]=f0.z; vf[3]=f0.w;
                vf[4]=f1.x; vf[5]=f1.y; vf[6]=f1.z; vf[7]=f1.w;
                vf[8]=f2.x; vf[9]=f2.y; vf[10]=f2.z; vf[11]=f2.w;
                vf[12]=f3.x; vf[13]=f3.y; vf[14]=f3.z; vf[15]=f3.w;
            }
        }

        #pragma unroll
        for (int ksub = 0; ksub < 32; ksub += 8) {
            uint32_t b0[4], b1[4];
            #pragma unroll
            for (int j = 0; j < 4; j++) {
                int nr = wn * 32 + j * 8 + g;
                b0[j] = *(const uint32_t*)&Bs[buf][nr][ksub + q];
                b1[j] = *(const uint32_t*)&Bs[buf][nr][ksub + q + 4];
            }
            #pragma unroll
            for (int i = 0; i < 4; i++) {
                int mr = wm * 64 + i * 16;
                uint32_t a0 = *(const uint32_t*)&As[mr + g][ksub + q];
                uint32_t a1 = *(const uint32_t*)&As[mr + 8 + g][ksub + q];
                uint32_t a2 = *(const uint32_t*)&As[mr + g][ksub + q + 4];
                uint32_t a3 = *(const uint32_t*)&As[mr + 8 + g][ksub + q + 4];
                #pragma unroll
                for (int j = 0; j < 4; j++)
                    mma_tf32(acc[i][j], a0, a1, a2, a3, b0[j], b1[j]);
            }
        }
        __syncthreads();
    }

    // epilogue: + bias, store fp16 Zh
    #pragma unroll
    for (int j = 0; j < 4; j++) {
        int cb = n0 + wn * 32 + j * 8 + q * 2;
        float2 bb = *(const float2*)&bias[cb];
        #pragma unroll
        for (int i = 0; i < 4; i++) {
            int r = m0 + wm * 64 + i * 16 + g;
            if (r < N_NODES) {
                __half2 o = __floats2half2_rn(acc[i][j][0] + bb.x, acc[i][j][1] + bb.y);
                *(__half2*)&g_Zh[(size_t)r * DIM + cb] = o;
            }
            if (r + 8 < N_NODES) {
                __half2 o = __floats2half2_rn(acc[i][j][2] + bb.x, acc[i][j][3] + bb.y);
                *(__half2*)&g_Zh[(size_t)(r + 8) * DIM + cb] = o;
            }
        }
    }
}

// ---------------- scan phase 1 (parametrized side) ---------------------------
__global__ void scan_p1_kernel(int which) {
    int n          = which ? N_NODES : N_EDGES;
    const int* deg = which ? g_deg_v : g_deg_e;
    int*  off      = which ? g_off_n : g_off_e;
    float* dinv    = which ? g_dv    : g_de;
    int*  part     = which ? g_part_n : g_part_e;

    int base = blockIdx.x * 1024;
    if (base >= n) return;
    int tid = threadIdx.x;
    int i = base + tid;
    int v = (i < n) ? deg[i] : 0;

    int x = v;
    int lane = tid & 31, warp = tid >> 5;
    #pragma unroll
    for (int s = 1; s < 32; s <<= 1) {
        int t = __shfl_up_sync(0xffffffffu, x, s);
        if (lane >= s) x += t;
    }
    __shared__ int wsum[32];
    if (lane == 31) wsum[warp] = x;
    __syncthreads();
    if (warp == 0) {
        int y = wsum[lane];
        #pragma unroll
        for (int s = 1; s < 32; s <<= 1) {
            int t = __shfl_up_sync(0xffffffffu, y, s);
            if (lane >= s) y += t;
        }
        wsum[lane] = y;
    }
    __syncthreads();
    int incl = x + (warp ? wsum[warp - 1] : 0);
    if (i < n) {
        off[i] = incl - v;
        dinv[i] = (v > 0) ? (which ? rsqrtf((float)v) : 1.0f / (float)v) : 0.0f;
    }
    if (tid == 1023) part[blockIdx.x] = incl;
}

// ---------------- scan phase 2 (parametrized side) ---------------------------
__global__ void scan_p2_kernel(int which) {
    __shared__ int p[64];
    int t = threadIdx.x;
    int nch = which ? CH_N : CH_E;
    int* part = which ? g_part_n : g_part_e;
    p[t] = (t < nch) ? part[t] : 0;
    __syncthreads();
    #pragma unroll
    for (int s = 1; s < 64; s <<= 1) {
        int v = (t >= s) ? p[t - s] : 0;
        __syncthreads();
        p[t] += v;
        __syncthreads();
    }
    part[t] = t ? p[t - 1] : 0;     // exclusive
    if (t == 0) {
        if (which) g_off_n[N_NODES] = NNZ;
        else       g_off_e[N_EDGES] = NNZ;
    }
}

// ---------------- scan phase 3 (parametrized side) ---------------------------
__global__ void scan_p3_kernel(int which) {
    int n    = which ? N_NODES : N_EDGES;
    int* off = which ? g_off_n : g_off_e;
    int i = blockIdx.x * 1024 + threadIdx.x;
    if (i < n) off[i] += (which ? g_part_n : g_part_e)[blockIdx.x];
}

// ---------------- CSR fill, edge side (atomic-free via ranks) ----------------
__global__ void fill_e_kernel(const void* ni, const void* ei) {
    int base = (blockIdx.x * blockDim.x + threadIdx.x) * 4;
    if (base >= NNZ) return;
    int is64 = g_is64;
    int n[4], e[4], r[4];
    #pragma unroll
    for (int u = 0; u < 4; u++) n[u] = idx_at(ni, base + u, is64);
    #pragma unroll
    for (int u = 0; u < 4; u++) e[u] = idx_at(ei, base + u, is64);
    #pragma unroll
    for (int u = 0; u < 4; u++) r[u] = g_rank_e[base + u];
    #pragma unroll
    for (int u = 0; u < 4; u++)
        g_adj_e[g_off_e[e[u]] + r[u]] = n[u];
}

// ---------------- CSR fill, node side (atomic-free via ranks) ----------------
__global__ void fill_n_kernel(const void* ni, const void* ei) {
    int base = (blockIdx.x * blockDim.x + threadIdx.x) * 4;
    if (base >= NNZ) return;
    int is64 = g_is64;
    int n[4], e[4], r[4];
    #pragma unroll
    for (int u = 0; u < 4; u++) n[u] = idx_at(ni, base + u, is64);
    #pragma unroll
    for (int u = 0; u < 4; u++) e[u] = idx_at(ei, base + u, is64);
    #pragma unroll
    for (int u = 0; u < 4; u++) r[u] = g_rank_v[base + u];
    #pragma unroll
    for (int u = 0; u < 4; u++)
        g_adj_n[g_off_n[n[u]] + r[u]] = e[u];
}

// ---------------- EG half: S2h[e, c0:c0+128] ---------------------------------
// one warp per edge; lane owns 4 contiguous fp16 columns (uint2 per row)
__global__ void edge_gather_half_kernel(int c0) {
    int w    = (blockIdx.x * blockDim.x + threadIdx.x) >> 5;
    int lane = threadIdx.x & 31;
    if (w >= N_EDGES) return;
    int s = g_off_e[w], e = g_off_e[w + 1];
    const __half* Zb = g_Zh + c0 + lane * 4;
    float a[4] = {0.f, 0.f, 0.f, 0.f};
    int j = s;
    int lim8 = s + ((e - s) & ~7);
    for (; j < lim8; j += 8) {
        int n[8]; float d[8]; uint2 v[8];
        #pragma unroll
        for (int u = 0; u < 8; u++) n[u] = g_adj_e[j + u];
        #pragma unroll
        for (int u = 0; u < 8; u++) d[u] = g_dv[n[u]];
        #pragma unroll
        for (int u = 0; u < 8; u++)
            v[u] = *(const uint2*)&Zb[(size_t)n[u] * DIM];
        #pragma unroll
        for (int u = 0; u < 8; u++) acc4(a, v[u], d[u]);
    }
    for (; j < e; j++) {
        int n0 = g_adj_e[j];
        uint2 v0 = *(const uint2*)&Zb[(size_t)n0 * DIM];
        acc4(a, v0, g_dv[n0]);
    }
    float de = g_de[w];
    __half2 o0 = __floats2half2_rn(a[0] * de, a[1] * de);
    __half2 o1 = __floats2half2_rn(a[2] * de, a[3] * de);
    uint2 st;
    st.x = *(uint32_t*)&o0; st.y = *(uint32_t*)&o1;
    *(uint2*)&g_S2h[(size_t)w * DIM + c0 + lane * 4] = st;
}

// ---------------- NG half: out[n, c0:c0+128] ---------------------------------
__global__ void node_gather_half_kernel(float* __restrict__ out_g, int c0) {
    int w    = (blockIdx.x * blockDim.x + threadIdx.x) >> 5;
    int lane = threadIdx.x & 31;
    if (w >= N_NODES) return;
    int s = g_off_n[w], e = g_off_n[w + 1];
    const __half* Sb = g_S2h + c0 + lane * 4;
    float a[4] = {0.f, 0.f, 0.f, 0.f};
    int j = s;
    int lim8 = s + ((e - s) & ~7);
    for (; j < lim8; j += 8) {
        int ee[8]; uint2 v[8];
        #pragma unroll
        for (int u = 0; u < 8; u++) ee[u] = g_adj_n[j + u];
        #pragma unroll
        for (int u = 0; u < 8; u++)
            v[u] = *(const uint2*)&Sb[(size_t)ee[u] * DIM];
        #pragma unroll
        for (int u = 0; u < 8; u++) acc4(a, v[u], 1.0f);
    }
    for (; j < e; j++) {
        int e0 = g_adj_n[j];
        uint2 v0 = *(const uint2*)&Sb[(size_t)e0 * DIM];
        acc4(a, v0, 1.0f);
    }
    float dv = g_dv[w];
    float4 o;
    o.x = a[0] * dv; o.y = a[1] * dv; o.z = a[2] * dv; o.w = a[3] * dv;
    *(float4*)&out_g[(size_t)w * DIM + c0 + lane * 4] = o;
}

// ---------------- launch: column-half pipelined DAG --------------------------
extern "C" void kernel_launch(void* const* d_in, const int* in_sizes, int n_in,
                              void* d_out, int out_size) {
    const float* X  = (const float*)d_in[0];
    const void*  ni = d_in[1];
    const void*  ei = d_in[2];
    const float* W  = (const float*)d_in[3];
    const float* b  = (const float*)d_in[4];
    float* out = (float*)d_out;

    static cudaStream_t sB = nullptr, sC = nullptr;
    static cudaEvent_t evRoot = nullptr, evG0 = nullptr, evCntE = nullptr,
                       evScanE = nullptr, evFillE = nullptr, evSV = nullptr,
                       evC = nullptr, evEG1 = nullptr;
    if (sB == nullptr) {
        cudaStreamCreateWithFlags(&sB, cudaStreamNonBlocking);
        cudaStreamCreateWithFlags(&sC, cudaStreamNonBlocking);
        cudaEventCreateWithFlags(&evRoot, cudaEventDisableTiming);
        cudaEventCreateWithFlags(&evG0, cudaEventDisableTiming);
        cudaEventCreateWithFlags(&evCntE, cudaEventDisableTiming);
        cudaEventCreateWithFlags(&evScanE, cudaEventDisableTiming);
        cudaEventCreateWithFlags(&evFillE, cudaEventDisableTiming);
        cudaEventCreateWithFlags(&evSV, cudaEventDisableTiming);
        cudaEventCreateWithFlags(&evC, cudaEventDisableTiming);
        cudaEventCreateWithFlags(&evEG1, cudaEventDisableTiming);
    }

    dim3 ggrid(N_PAD / 128, 1);
    int eg_blocks = (N_EDGES * 32 + 255) / 256;
    int ng_blocks = (N_NODES * 32 + 255) / 256;

    // fork: sB branches off the main (capture) stream at the root
    cudaEventRecord(evRoot, 0);
    cudaStreamWaitEvent(sB, evRoot, 0);

    // ---- chain B (sB): W convert + GEMM halves ----
    convert_w_kernel<<<DIM, DIM, 0, sB>>>(W);
    gemm_tf32_kernel<<<ggrid, 256, 0, sB>>>(X, b, 0);
    cudaEventRecord(evG0, sB);
    gemm_tf32_kernel<<<ggrid, 256, 0, sB>>>(X, b, 128);

    // ---- chain A (main): detect -> count_e -> scanE -> fill_e ----
    detect_kernel<<<1, 32>>>(ni);
    count_e_kernel<<<(NNZ + 255) / 256, 256>>>(ei);
    cudaEventRecord(evCntE, 0);
    scan_p1_kernel<<<CH_E, 1024>>>(0);
    scan_p2_kernel<<<1, 64>>>(0);
    scan_p3_kernel<<<CH_E, 1024>>>(0);
    cudaEventRecord(evScanE, 0);
    fill_e_kernel<<<(NNZ / 4 + 255) / 256, 256>>>(ni, ei);
    cudaEventRecord(evFillE, 0);

    // ---- chain C (sC): v-side, sequenced after count_e ----
    cudaStreamWaitEvent(sC, evCntE, 0);
    count_v_kernel<<<(NNZ + 255) / 256, 256, 0, sC>>>(ni);
    scan_p1_kernel<<<CH_N, 1024, 0, sC>>>(1);
    cudaEventRecord(evSV, sC);                    // g_dv ready
    scan_p2_kernel<<<1, 64, 0, sC>>>(1);
    scan_p3_kernel<<<CH_N, 1024, 0, sC>>>(1);
    fill_n_kernel<<<(NNZ / 4 + 255) / 256, 256, 0, sC>>>(ni, ei);
    cudaStreamWaitEvent(sC, evScanE, 0);          // deg_e consumed before zero
    zero_kernel<<<(N_NODES + 255) / 256, 256, 0, sC>>>();
    cudaEventRecord(evC, sC);

    // ---- sB continues: EG half 1 (after GEMM1 in-stream, needs fill_e + dv)
    cudaStreamWaitEvent(sB, evFillE, 0);
    cudaStreamWaitEvent(sB, evSV, 0);
    edge_gather_half_kernel<<<eg_blocks, 256, 0, sB>>>(128);
    cudaEventRecord(evEG1, sB);

    // ---- main: EG half 0 (needs GEMM0 + dv), then NG halves ----
    cudaStreamWaitEvent(0, evG0, 0);
    cudaStreamWaitEvent(0, evSV, 0);
    edge_gather_half_kernel<<<eg_blocks, 256>>>(0);

    cudaStreamWaitEvent(0, evC, 0);               // adj_n + zero done
    node_gather_half_kernel<<<ng_blocks, 256>>>(out, 0);

    cudaStreamWaitEvent(0, evEG1, 0);             // join sB tail
    node_gather_half_kernel<<<ng_blocks, 256>>>(out, 128);
}